// round 10
// baseline (speedup 1.0000x reference)
#include <cuda_runtime.h>
#include <cstddef>

#define BB 2
#define TT 2048
#define DD 1024
#define HH 16
#define HD 64
#define TD3 (3*DD)

// Scratch (device globals: allowed; cudaMalloc is not)
__device__ float g_res[(size_t)BB*TT*TD3];        // QKV projection (tf32-rounded)
__device__ float g_ctx[(size_t)BB*TT*DD];         // context (tf32-rounded)
__device__ float g_attn[(size_t)BB*HH*TT*TT];     // attn fallback
__device__ float g_Xr[(size_t)BB*TT*DD];          // X tf32-rounded
__device__ float g_WtKQV[(size_t)TD3*DD];         // W_KQV^T [3D][D] tf32-rounded
__device__ float g_WtOut[(size_t)DD*DD];          // W_out^T [D][D] tf32-rounded
__device__ float g_inv[(size_t)BB*HH*TT];         // per-row 1/softmax-sum

// ---------------------------------------------------------------------------
// helpers
// ---------------------------------------------------------------------------
__device__ __forceinline__ unsigned f2tf(float f) {
    unsigned r; asm("cvt.rna.tf32.f32 %0, %1;" : "=r"(r) : "f"(f)); return r;
}
__device__ __forceinline__ float f2tf_f(float f) {
    unsigned r = f2tf(f); return __uint_as_float(r);
}
__device__ __forceinline__ void mma_tf32(float* c, const unsigned* a, const unsigned* b) {
    asm volatile("mma.sync.aligned.m16n8k8.row.col.f32.tf32.tf32.f32 "
        "{%0,%1,%2,%3}, {%4,%5,%6,%7}, {%8,%9}, {%0,%1,%2,%3};"
        : "+f"(c[0]), "+f"(c[1]), "+f"(c[2]), "+f"(c[3])
        : "r"(a[0]), "r"(a[1]), "r"(a[2]), "r"(a[3]), "r"(b[0]), "r"(b[1]));
}
__device__ __forceinline__ unsigned smem_u32(const void* p) {
    return (unsigned)__cvta_generic_to_shared(p);
}
__device__ __forceinline__ void cp16(unsigned dst, const void* src) {
    asm volatile("cp.async.cg.shared.global [%0], [%1], 16;" :: "r"(dst), "l"(src));
}
#define CP_COMMIT() asm volatile("cp.async.commit_group;" ::: "memory")
#define CP_WAIT1()  asm volatile("cp.async.wait_group 1;" ::: "memory")
#define CP_WAIT0()  asm volatile("cp.async.wait_group 0;" ::: "memory")

__device__ __forceinline__ void ldsm_x4(unsigned* r, unsigned addr) {
    asm volatile("ldmatrix.sync.aligned.m8n8.x4.shared.b16 {%0,%1,%2,%3}, [%4];"
        : "=r"(r[0]), "=r"(r[1]), "=r"(r[2]), "=r"(r[3]) : "r"(addr));
}
__device__ __forceinline__ void ldsm_x2(unsigned* r, unsigned addr) {
    asm volatile("ldmatrix.sync.aligned.m8n8.x2.shared.b16 {%0,%1}, [%2];"
        : "=r"(r[0]), "=r"(r[1]) : "r"(addr));
}

// ---------------------------------------------------------------------------
// prep kernels
// ---------------------------------------------------------------------------
__global__ __launch_bounds__(256) void round_copy(
    const float* __restrict__ in, float* __restrict__ out, int n4)
{
    int i = blockIdx.x * 256 + threadIdx.x;
    int stride = gridDim.x * 256;
    for (; i < n4; i += stride) {
        float4 v = *(const float4*)(in + (size_t)i * 4);
        v.x = f2tf_f(v.x); v.y = f2tf_f(v.y); v.z = f2tf_f(v.z); v.w = f2tf_f(v.w);
        *(float4*)(out + (size_t)i * 4) = v;
    }
}

// in[R][C] -> out[C][R], tf32-rounded
__global__ __launch_bounds__(256) void transpose_round(
    const float* __restrict__ in, float* __restrict__ out, int R, int C)
{
    __shared__ float t[32][33];
    int bx = blockIdx.x * 32;   // C
    int by = blockIdx.y * 32;   // R
    int tx = threadIdx.x & 31, ty = threadIdx.x >> 5;
    #pragma unroll
    for (int i = 0; i < 4; i++)
        t[ty + i*8][tx] = in[(size_t)(by + ty + i*8) * C + bx + tx];
    __syncthreads();
    #pragma unroll
    for (int i = 0; i < 4; i++)
        out[(size_t)(bx + ty + i*8) * R + by + tx] = f2tf_f(t[tx][ty + i*8]);
}

// ---------------------------------------------------------------------------
// NT tf32 GEMM: C[M,N] = A[M,K] @ Bt[N,K]^T, both K-major, pre-rounded tf32.
// 3-stage cp.async; ALL fragments via ldmatrix. block 128x128, k-stage 32.
// ---------------------------------------------------------------------------
#define GA_SZ (128*36)
#define GB_SZ (128*36)
#define GEMM_SMEM ((3*GA_SZ + 3*GB_SZ) * 4)   // 110,592 B

__global__ __launch_bounds__(256, 2) void gemm_tf32_nt(
    const float* __restrict__ A, const float* __restrict__ Bt,
    float* __restrict__ C, int M, int N, int K, int round_out)
{
    extern __shared__ float gsm[];
    float* Asf = gsm;               // [3][128][36]
    float* Bsf = gsm + 3*GA_SZ;     // [3][128][36]

    int tid = threadIdx.x;
    int lane = tid & 31, wid = tid >> 5;
    int wm = (wid >> 2) * 64;
    int wn = (wid & 3) * 32;
    int g  = lane >> 2, tg = lane & 3;

    size_t by = (size_t)blockIdx.y * 128;
    size_t bx = (size_t)blockIdx.x * 128;

    int ar = tid >> 1, aj = tid & 1;
    const float* Ab = A  + (by + ar) * K;
    const float* Bb = Bt + (bx + ar) * K;

    int mat = lane >> 3, rowin = lane & 7;
    int l16 = lane & 15;
    unsigned a_off[4], b_off[4];
    #pragma unroll
    for (int mt = 0; mt < 4; mt++)
        a_off[mt] = (unsigned)(((wm + mt*16 + (mat & 1)*8 + rowin) * 36
                                + (mat >> 1) * 4) * 4);
    #pragma unroll
    for (int nt = 0; nt < 4; nt++)
        b_off[nt] = (unsigned)(((wn + nt*8 + (l16 & 7)) * 36
                                + (l16 >> 3) * 4) * 4);
    unsigned asb = smem_u32(Asf);
    unsigned bsb = smem_u32(Bsf);

    float acc[4][4][4];
    #pragma unroll
    for (int i = 0; i < 4; i++)
        #pragma unroll
        for (int j = 0; j < 4; j++)
            #pragma unroll
            for (int f = 0; f < 4; f++) acc[i][j][f] = 0.f;

    auto load_stage = [&](int s, int k0) {
        unsigned ab = smem_u32(&Asf[s*GA_SZ + ar*36]);
        unsigned bb = smem_u32(&Bsf[s*GB_SZ + ar*36]);
        const float* asrc = Ab + k0;
        const float* bsrc = Bb + k0;
        #pragma unroll
        for (int i = 0; i < 4; i++) {
            int c4 = aj + 2*i;
            cp16(ab + c4*16, asrc + c4*4);
            cp16(bb + c4*16, bsrc + c4*4);
        }
    };

    const int NIT = K >> 5;
    load_stage(0, 0);  CP_COMMIT();
    load_stage(1, 32); CP_COMMIT();

    #pragma unroll 1
    for (int it = 0; it < NIT; it++) {
        CP_WAIT1();
        __syncthreads();
        if (it + 2 < NIT) load_stage((it + 2) % 3, (it + 2) << 5);
        CP_COMMIT();

        unsigned abase = asb + (unsigned)((it % 3) * GA_SZ * 4);
        unsigned bbase = bsb + (unsigned)((it % 3) * GB_SZ * 4);
        #pragma unroll
        for (int ks = 0; ks < 4; ks++) {
            unsigned kbyte = (unsigned)(ks * 32);
            unsigned a[4][4], b[4][2];
            #pragma unroll
            for (int mt = 0; mt < 4; mt++)
                ldsm_x4(a[mt], abase + a_off[mt] + kbyte);
            #pragma unroll
            for (int nt = 0; nt < 4; nt++)
                ldsm_x2(b[nt], bbase + b_off[nt] + kbyte);
            #pragma unroll
            for (int mt = 0; mt < 4; mt++)
                #pragma unroll
                for (int nt = 0; nt < 4; nt++)
                    mma_tf32(acc[mt][nt], a[mt], b[nt]);
        }
    }

    #pragma unroll
    for (int mt = 0; mt < 4; mt++) {
        #pragma unroll
        for (int nt = 0; nt < 4; nt++) {
            size_t r = by + wm + mt * 16 + g;
            size_t c = bx + wn + nt * 8 + tg * 2;
            float v0 = acc[mt][nt][0], v1 = acc[mt][nt][1];
            float v2 = acc[mt][nt][2], v3 = acc[mt][nt][3];
            if (round_out) {
                v0 = f2tf_f(v0); v1 = f2tf_f(v1); v2 = f2tf_f(v2); v3 = f2tf_f(v3);
            }
            *(float2*)(C + r * N + c)       = make_float2(v0, v1);
            *(float2*)(C + (r + 8) * N + c) = make_float2(v2, v3);
        }
    }
}

// ---------------------------------------------------------------------------
// Fused attention PASS 1 ONLY: rowsums + ctx; exports inv to g_inv.
// ---------------------------------------------------------------------------
#define KS_STRIDE 68
#define ES_STRIDE 132
#define QS_STRIDE 68
#define VS_STRIDE 72
#define OFF_ES 8704
#define OFF_Q0 25600
#define OFF_Q1 34304
#define OFF_V  43008
#define OFF_RP 52224
#define OFF_INV 52736
#define ATTN_SMEM ((OFF_INV + 128 + 64) * 4)   // 211,712 B

__global__ __launch_bounds__(256) void attn_fused(
    const float* __restrict__ res, float* __restrict__ ctx,
    float* __restrict__ inv_g)
{
    extern __shared__ unsigned sm[];
    unsigned* Ks = sm;
    unsigned* Es = sm + OFF_ES;
    unsigned* Qb0 = sm + OFF_Q0;
    unsigned* Qb1 = sm + OFF_Q1;
    unsigned* Vsu = sm + OFF_V;
    float* rp    = (float*)(sm + OFF_RP);
    float* inv_s = (float*)(sm + OFF_INV);

    int kb = (TT/128 - 1) - blockIdx.x;
    int bh = blockIdx.y;
    int b = bh / HH, h = bh % HH;
    int tid = threadIdx.x;
    int lane = tid & 31, wid = tid >> 5;
    int wm = (wid >> 2) * 64, wn = (wid & 3) * 32;
    int wm2 = (wid >> 1) * 32, wn2 = (wid & 1) * 32;
    int g = lane >> 2, tg = lane & 3;

    const float* Kg = res + (size_t)b * TT * TD3 + (size_t)h * HD;
    const float* Qg = res + (size_t)b * TT * TD3 + DD + (size_t)h * HD;
    const float* Vg = res + (size_t)b * TT * TD3 + 2 * DD + (size_t)h * HD;

    int qr = tid >> 1, qj = tid & 1;

    int mat = lane >> 3, rowin = lane & 7;
    int l16 = lane & 15;
    unsigned ks_off[4], es_off[2], q_off[4];
    #pragma unroll
    for (int mt = 0; mt < 4; mt++)
        ks_off[mt] = (unsigned)(((wm + mt*16 + (mat & 1)*8 + rowin) * KS_STRIDE
                                 + (mat >> 1) * 4) * 4);
    #pragma unroll
    for (int mt = 0; mt < 2; mt++)
        es_off[mt] = (unsigned)(((wm2 + mt*16 + (mat & 1)*8 + rowin) * ES_STRIDE
                                 + (mat >> 1) * 4) * 4);
    #pragma unroll
    for (int nt = 0; nt < 4; nt++)
        q_off[nt] = (unsigned)(((wn + nt*8 + (l16 & 7)) * QS_STRIDE
                                + (l16 >> 3) * 4) * 4);
    unsigned ksb = smem_u32(Ks);
    unsigned esb = smem_u32(Es);
    unsigned q0b = smem_u32(Qb0);
    unsigned q1b = smem_u32(Qb1);

    auto loadQ = [&](unsigned* buf, int qb) {
        unsigned base = smem_u32(&buf[qr * QS_STRIDE]);
        const float* src = Qg + (size_t)(qb * 128 + qr) * TD3;
        #pragma unroll
        for (int i = 0; i < 8; i++) {
            int c4 = qj + 2*i;
            cp16(base + c4*16, src + c4*4);
        }
    };
    auto loadV = [&](int qb) {
        unsigned base = smem_u32(&Vsu[qr * VS_STRIDE]);
        const float* src = Vg + (size_t)(qb * 128 + qr) * TD3;
        #pragma unroll
        for (int i = 0; i < 8; i++) {
            int c4 = qj + 2*i;
            cp16(base + c4*16, src + c4*4);
        }
    };

    // Stage K tile (already tf32 bits)
    {
        #pragma unroll
        for (int i = 0; i < 8; i++) {
            int ak = qj * 4 + i * 8;
            float4 v = *(const float4*)(Kg + (size_t)(kb * 128 + qr) * TD3 + ak);
            Ks[qr*KS_STRIDE + ak+0] = __float_as_uint(v.x);
            Ks[qr*KS_STRIDE + ak+1] = __float_as_uint(v.y);
            Ks[qr*KS_STRIDE + ak+2] = __float_as_uint(v.z);
            Ks[qr*KS_STRIDE + ak+3] = __float_as_uint(v.w);
        }
    }

    float rs0[4] = {0.f,0.f,0.f,0.f}, rs1[4] = {0.f,0.f,0.f,0.f};
    float acc2[2][4][4];
    #pragma unroll
    for (int i = 0; i < 2; i++)
        #pragma unroll
        for (int j = 0; j < 4; j++)
            #pragma unroll
            for (int f = 0; f < 4; f++) acc2[i][j][f] = 0.f;

    const float scale = 0.125f;

    loadQ(Qb0, 0); CP_COMMIT();
    #pragma unroll 1
    for (int qb = 0; qb <= kb; qb++) {
        unsigned qcb = (qb & 1) ? q1b : q0b;
        unsigned* Qnxt = (qb & 1) ? Qb0 : Qb1;
        loadV(qb); CP_COMMIT();
        CP_WAIT1();
        __syncthreads();

        float acc[4][4][4];
        #pragma unroll
        for (int i = 0; i < 4; i++)
            #pragma unroll
            for (int j = 0; j < 4; j++)
                #pragma unroll
                for (int f = 0; f < 4; f++) acc[i][j][f] = 0.f;

        #pragma unroll 4
        for (int ks = 0; ks < 8; ks++) {
            unsigned kbyte = (unsigned)(ks * 32);
            unsigned a[4][4], bf[4][2];
            #pragma unroll
            for (int mt = 0; mt < 4; mt++)
                ldsm_x4(a[mt], ksb + ks_off[mt] + kbyte);
            #pragma unroll
            for (int nt = 0; nt < 4; nt++)
                ldsm_x2(bf[nt], qcb + q_off[nt] + kbyte);
            #pragma unroll
            for (int mt = 0; mt < 4; mt++)
                #pragma unroll
                for (int nt = 0; nt < 4; nt++)
                    mma_tf32(acc[mt][nt], a[mt], bf[nt]);
        }

        if (qb < kb) loadQ(Qnxt, qb + 1);
        CP_COMMIT();

        bool diag = (qb == kb);
        #pragma unroll
        for (int mt = 0; mt < 4; mt++) {
            #pragma unroll
            for (int nt = 0; nt < 4; nt++) {
                int r = wm + mt * 16 + g;
                int c = wn + nt * 8 + tg * 2;
                int rg0 = kb * 128 + r, rg1 = rg0 + 8;
                int cg  = qb * 128 + c;
                float e0 = (diag && cg     > rg0) ? 0.f : __expf(acc[mt][nt][0] * scale);
                float e1 = (diag && cg + 1 > rg0) ? 0.f : __expf(acc[mt][nt][1] * scale);
                float e2 = (diag && cg     > rg1) ? 0.f : __expf(acc[mt][nt][2] * scale);
                float e3 = (diag && cg + 1 > rg1) ? 0.f : __expf(acc[mt][nt][3] * scale);
                rs0[mt] += e0 + e1;
                rs1[mt] += e2 + e3;
                *(uint2*)&Es[r*ES_STRIDE + c]     = make_uint2(f2tf(e0), f2tf(e1));
                *(uint2*)&Es[(r+8)*ES_STRIDE + c] = make_uint2(f2tf(e2), f2tf(e3));
            }
        }
        CP_WAIT1();
        __syncthreads();

        #pragma unroll 4
        for (int ks = 0; ks < 16; ks++) {
            int k8 = ks * 8;
            unsigned a[2][4], bf[4][2];
            #pragma unroll
            for (int mt = 0; mt < 2; mt++)
                ldsm_x4(a[mt], esb + es_off[mt] + (unsigned)(k8 * 4));
            #pragma unroll
            for (int nt = 0; nt < 4; nt++) {
                int c = wn2 + nt * 8 + g;
                bf[nt][0] = Vsu[(k8+tg)*VS_STRIDE + c];
                bf[nt][1] = Vsu[(k8+tg+4)*VS_STRIDE + c];
            }
            #pragma unroll
            for (int mt = 0; mt < 2; mt++)
                #pragma unroll
                for (int nt = 0; nt < 4; nt++)
                    mma_tf32(acc2[mt][nt], a[mt], bf[nt]);
        }
        __syncthreads();
    }

    // rowsum reduce -> inv (smem + export to global)
    #pragma unroll
    for (int mt = 0; mt < 4; mt++) {
        float s0 = rs0[mt], s1 = rs1[mt];
        s0 += __shfl_xor_sync(0xffffffffu, s0, 1);
        s0 += __shfl_xor_sync(0xffffffffu, s0, 2);
        s1 += __shfl_xor_sync(0xffffffffu, s1, 1);
        s1 += __shfl_xor_sync(0xffffffffu, s1, 2);
        if (tg == 0) {
            rp[(wm + mt*16 + g)*4 + (wid & 3)]     = s0;
            rp[(wm + mt*16 + g + 8)*4 + (wid & 3)] = s1;
        }
    }
    __syncthreads();
    if (tid < 128) {
        float iv = 1.f / (rp[tid*4] + rp[tid*4+1] + rp[tid*4+2] + rp[tid*4+3]);
        inv_s[tid] = iv;
        inv_g[(size_t)bh * TT + kb * 128 + tid] = iv;
    }
    __syncthreads();

    // scale ctx, write tf32-rounded (consumed by tensor out-GEMM)
    {
        float* Cg = ctx + (size_t)b * TT * DD + (size_t)h * HD;
        #pragma unroll
        for (int mt = 0; mt < 2; mt++) {
            int r2 = wm2 + mt * 16 + g;
            float il = inv_s[r2], ih = inv_s[r2 + 8];
            #pragma unroll
            for (int nt = 0; nt < 4; nt++) {
                size_t rA = (size_t)kb * 128 + r2;
                int c = wn2 + nt * 8 + tg * 2;
                *(float2*)(Cg + rA * DD + c) =
                    make_float2(f2tf_f(acc2[mt][nt][0] * il), f2tf_f(acc2[mt][nt][1] * il));
                *(float2*)(Cg + (rA + 8) * DD + c) =
                    make_float2(f2tf_f(acc2[mt][nt][2] * ih), f2tf_f(acc2[mt][nt][3] * ih));
            }
        }
    }
}

// ---------------------------------------------------------------------------
// attn_write: one 128x128 tile per CTA. Zero tiles early-exit; compute tiles
// recompute scores (res L2-resident), apply exp*inv, write attn once.
// Bit-identical mma order to pass 1. 2 CTAs/SM.
// ---------------------------------------------------------------------------
#define AW_QS 8704
#define AW_SMEM (2 * 8704 * 4)   // 69,632 B

__global__ __launch_bounds__(256, 2) void attn_write(
    const float* __restrict__ res, const float* __restrict__ inv_g,
    float* __restrict__ attn)
{
    extern __shared__ unsigned sm2[];
    unsigned* Ks = sm2;
    unsigned* Qs = sm2 + AW_QS;

    int qb = blockIdx.x, kb = blockIdx.y, bh = blockIdx.z;
    int b = bh / HH, h = bh % HH;
    int tid = threadIdx.x;
    float* out = attn + ((size_t)bh * TT + (size_t)kb * 128) * TT + (size_t)qb * 128;

    if (qb > kb) {   // fully masked -> zeros
        float4 z = make_float4(0.f, 0.f, 0.f, 0.f);
        #pragma unroll
        for (int i = tid; i < 128 * 32; i += 256)
            *(float4*)(out + (size_t)(i >> 5) * TT + (i & 31) * 4) = z;
        return;
    }

    int lane = tid & 31, wid = tid >> 5;
    int wm = (wid >> 2) * 64, wn = (wid & 3) * 32;
    int g = lane >> 2, tg = lane & 3;

    const float* Kg = res + (size_t)b * TT * TD3 + (size_t)h * HD;
    const float* Qg = res + (size_t)b * TT * TD3 + DD + (size_t)h * HD;

    int qr = tid >> 1, qj = tid & 1;
    {
        unsigned kb_s = smem_u32(&Ks[qr * KS_STRIDE]);
        unsigned qb_s = smem_u32(&Qs[qr * QS_STRIDE]);
        const float* ksrc = Kg + (size_t)(kb * 128 + qr) * TD3;
        const float* qsrc = Qg + (size_t)(qb * 128 + qr) * TD3;
        #pragma unroll
        for (int i = 0; i < 8; i++) {
            int c4 = qj + 2*i;
            cp16(kb_s + c4*16, ksrc + c4*4);
            cp16(qb_s + c4*16, qsrc + c4*4);
        }
    }
    CP_COMMIT();

    int mat = lane >> 3, rowin = lane & 7;
    int l16 = lane & 15;
    unsigned ks_off[4], q_off[4];
    #pragma unroll
    for (int mt = 0; mt < 4; mt++)
        ks_off[mt] = (unsigned)(((wm + mt*16 + (mat & 1)*8 + rowin) * KS_STRIDE
                                 + (mat >> 1) * 4) * 4);
    #pragma unroll
    for (int nt = 0; nt < 4; nt++)
        q_off[nt] = (unsigned)(((wn + nt*8 + (l16 & 7)) * QS_STRIDE
                                + (l16 >> 3) * 4) * 4);
    unsigned ksb = smem_u32(Ks);
    unsigned qsb = smem_u32(Qs);

    float iv0[4], iv1[4];
    #pragma unroll
    for (int mt = 0; mt < 4; mt++) {
        iv0[mt] = inv_g[(size_t)bh * TT + kb * 128 + wm + mt*16 + g];
        iv1[mt] = inv_g[(size_t)bh * TT + kb * 128 + wm + mt*16 + g + 8];
    }

    CP_WAIT0();
    __syncthreads();

    float acc[4][4][4];
    #pragma unroll
    for (int i = 0; i < 4; i++)
        #pragma unroll
        for (int j = 0; j < 4; j++)
            #pragma unroll
            for (int f = 0; f < 4; f++) acc[i][j][f] = 0.f;

    #pragma unroll 4
    for (int ks = 0; ks < 8; ks++) {
        unsigned kbyte = (unsigned)(ks * 32);
        unsigned a[4][4], bf[4][2];
        #pragma unroll
        for (int mt = 0; mt < 4; mt++)
            ldsm_x4(a[mt], ksb + ks_off[mt] + kbyte);
        #pragma unroll
        for (int nt = 0; nt < 4; nt++)
            ldsm_x2(bf[nt], qsb + q_off[nt] + kbyte);
        #pragma unroll
        for (int mt = 0; mt < 4; mt++)
            #pragma unroll
            for (int nt = 0; nt < 4; nt++)
                mma_tf32(acc[mt][nt], a[mt], bf[nt]);
    }

    const float scale = 0.125f;
    bool diag = (qb == kb);
    #pragma unroll
    for (int mt = 0; mt < 4; mt++) {
        #pragma unroll
        for (int nt = 0; nt < 4; nt++) {
            int r = wm + mt * 16 + g;
            int c = wn + nt * 8 + tg * 2;
            int rg0 = kb * 128 + r, rg1 = rg0 + 8;
            int cg  = qb * 128 + c;
            float e0 = (diag && cg     > rg0) ? 0.f : __expf(acc[mt][nt][0]*scale) * iv0[mt];
            float e1 = (diag && cg + 1 > rg0) ? 0.f : __expf(acc[mt][nt][1]*scale) * iv0[mt];
            float e2 = (diag && cg     > rg1) ? 0.f : __expf(acc[mt][nt][2]*scale) * iv1[mt];
            float e3 = (diag && cg + 1 > rg1) ? 0.f : __expf(acc[mt][nt][3]*scale) * iv1[mt];
            *(float2*)(out + (size_t)r * TT + c)       = make_float2(e0, e1);
            *(float2*)(out + (size_t)(r + 8) * TT + c) = make_float2(e2, e3);
        }
    }
}

// ---------------------------------------------------------------------------
extern "C" void kernel_launch(void* const* d_in, const int* in_sizes, int n_in,
                              void* d_out, int out_size)
{
    const float* X     = (const float*)d_in[0];
    const float* W_KQV = (const float*)d_in[1];
    const float* W_out = (const float*)d_in[2];

    const size_t OUT_E  = (size_t)BB * TT * DD;
    const size_t ATTN_E = (size_t)BB * HH * TT * TT;

    float* res_p;  cudaGetSymbolAddress((void**)&res_p,  g_res);
    float* ctx_p;  cudaGetSymbolAddress((void**)&ctx_p,  g_ctx);
    float* attn_s; cudaGetSymbolAddress((void**)&attn_s, g_attn);
    float* xr_p;   cudaGetSymbolAddress((void**)&xr_p,   g_Xr);
    float* wtk_p;  cudaGetSymbolAddress((void**)&wtk_p,  g_WtKQV);
    float* wto_p;  cudaGetSymbolAddress((void**)&wto_p,  g_WtOut);
    float* inv_p;  cudaGetSymbolAddress((void**)&inv_p,  g_inv);

    float* out_p = nullptr;
    float* attn_p;
    size_t osz = (size_t)out_size;
    if (osz >= OUT_E + ATTN_E) {
        out_p  = (float*)d_out;
        attn_p = (float*)d_out + OUT_E;
    } else if (osz == ATTN_E) {
        attn_p = (float*)d_out;
    } else {
        out_p  = (float*)d_out;
        attn_p = attn_s;
    }

    cudaFuncSetAttribute(gemm_tf32_nt,
                         cudaFuncAttributeMaxDynamicSharedMemorySize, GEMM_SMEM);
    cudaFuncSetAttribute(attn_fused,
                         cudaFuncAttributeMaxDynamicSharedMemorySize, ATTN_SMEM);
    cudaFuncSetAttribute(attn_write,
                         cudaFuncAttributeMaxDynamicSharedMemorySize, AW_SMEM);

    // 0) prep: tf32-round X; transpose+round weights to [N][K]
    round_copy<<<512, 256>>>(X, xr_p, (BB*TT*DD) / 4);
    {
        dim3 grid(TD3 / 32, DD / 32);
        transpose_round<<<grid, 256>>>(W_KQV, wtk_p, DD, TD3);
    }
    {
        dim3 grid(DD / 32, DD / 32);
        transpose_round<<<grid, 256>>>(W_out, wto_p, DD, DD);
    }

    // 1) QKV projection (writes res tf32-rounded)
    {
        dim3 grid(TD3 / 128, (BB * TT) / 128);
        gemm_tf32_nt<<<grid, 256, GEMM_SMEM>>>(xr_p, wtk_p, res_p, BB * TT, TD3, DD, 1);
    }
    // 2) pass 1: ctx (tf32-rounded) + inv export
    {
        dim3 grid(TT / 128, BB * HH);
        attn_fused<<<grid, 256, ATTN_SMEM>>>(res_p, ctx_p, inv_p);
    }
    // 3) write normalized attn (one tile per CTA, high occupancy)
    {
        dim3 grid(TT / 128, TT / 128, BB * HH);
        attn_write<<<grid, 256, AW_SMEM>>>(res_p, inv_p, attn_p);
    }
    // 4) out = ctx @ W_out (full fp32 output)
    if (out_p) {
        dim3 grid(DD / 128, (BB * TT) / 128);
        gemm_tf32_nt<<<grid, 256, GEMM_SMEM>>>(ctx_p, wto_p, out_p, BB * TT, DD, DD, 0);
    }
}

// round 11
// speedup vs baseline: 1.0592x; 1.0592x over previous
#include <cuda_runtime.h>
#include <cstddef>

#define BB 2
#define TT 2048
#define DD 1024
#define HH 16
#define HD 64
#define TD3 (3*DD)

// Scratch (device globals: allowed; cudaMalloc is not)
__device__ float g_res[(size_t)BB*TT*TD3];        // QKV projection (tf32-rounded)
__device__ float g_ctx[(size_t)BB*TT*DD];         // context (tf32-rounded)
__device__ float g_attn[(size_t)BB*HH*TT*TT];     // attn fallback
__device__ float g_Xr[(size_t)BB*TT*DD];          // X tf32-rounded
__device__ float g_WrKQV[(size_t)DD*TD3];         // W_KQV tf32-rounded [K,N]
__device__ float g_WrOut[(size_t)DD*DD];          // W_out tf32-rounded [K,N]
__device__ float g_inv[(size_t)BB*HH*TT];         // per-row 1/softmax-sum

// ---------------------------------------------------------------------------
// helpers
// ---------------------------------------------------------------------------
__device__ __forceinline__ unsigned f2tf(float f) {
    unsigned r; asm("cvt.rna.tf32.f32 %0, %1;" : "=r"(r) : "f"(f)); return r;
}
__device__ __forceinline__ float f2tf_f(float f) {
    unsigned r = f2tf(f); return __uint_as_float(r);
}
__device__ __forceinline__ void mma_tf32(float* c, const unsigned* a, const unsigned* b) {
    asm volatile("mma.sync.aligned.m16n8k8.row.col.f32.tf32.tf32.f32 "
        "{%0,%1,%2,%3}, {%4,%5,%6,%7}, {%8,%9}, {%0,%1,%2,%3};"
        : "+f"(c[0]), "+f"(c[1]), "+f"(c[2]), "+f"(c[3])
        : "r"(a[0]), "r"(a[1]), "r"(a[2]), "r"(a[3]), "r"(b[0]), "r"(b[1]));
}
__device__ __forceinline__ unsigned smem_u32(const void* p) {
    return (unsigned)__cvta_generic_to_shared(p);
}
__device__ __forceinline__ void cp16(unsigned dst, const void* src) {
    asm volatile("cp.async.cg.shared.global [%0], [%1], 16;" :: "r"(dst), "l"(src));
}
#define CP_COMMIT() asm volatile("cp.async.commit_group;" ::: "memory")
#define CP_WAIT1()  asm volatile("cp.async.wait_group 1;" ::: "memory")
#define CP_WAIT0()  asm volatile("cp.async.wait_group 0;" ::: "memory")

__device__ __forceinline__ void ldsm_x4(unsigned* r, unsigned addr) {
    asm volatile("ldmatrix.sync.aligned.m8n8.x4.shared.b16 {%0,%1,%2,%3}, [%4];"
        : "=r"(r[0]), "=r"(r[1]), "=r"(r[2]), "=r"(r[3]) : "r"(addr));
}
__device__ __forceinline__ void ldsm_x2(unsigned* r, unsigned addr) {
    asm volatile("ldmatrix.sync.aligned.m8n8.x2.shared.b16 {%0,%1}, [%2];"
        : "=r"(r[0]), "=r"(r[1]) : "r"(addr));
}

// ---------------------------------------------------------------------------
// prep: tf32-round a contiguous array
// ---------------------------------------------------------------------------
__global__ __launch_bounds__(256) void round_copy(
    const float* __restrict__ in, float* __restrict__ out, int n4)
{
    int i = blockIdx.x * 256 + threadIdx.x;
    int stride = gridDim.x * 256;
    for (; i < n4; i += stride) {
        float4 v = *(const float4*)(in + (size_t)i * 4);
        v.x = f2tf_f(v.x); v.y = f2tf_f(v.y); v.z = f2tf_f(v.z); v.w = f2tf_f(v.w);
        *(float4*)(out + (size_t)i * 4) = v;
    }
}

// ---------------------------------------------------------------------------
// NN tf32 GEMM (R9 version — fastest measured): 3-stage cp.async pipeline,
// ldmatrix A-fragments, scalar conflict-free B-fragments.
// C[M,N]=A[M,K]@B[K,N] row-major, inputs pre-rounded tf32 bits.
// ---------------------------------------------------------------------------
#define GA_SZ (128*36)
#define GB_SZ (32*136)
#define GEMM_SMEM ((3*GA_SZ + 3*GB_SZ) * 4)   // 107,520 B

__global__ __launch_bounds__(256, 2) void gemm_tf32_nn(
    const float* __restrict__ A, const float* __restrict__ B,
    float* __restrict__ C, int M, int N, int K, int round_out)
{
    extern __shared__ float gsm[];
    float* Asf = gsm;               // [3][128][36]
    float* Bsf = gsm + 3*GA_SZ;     // [3][32][136]

    int tid = threadIdx.x;
    int lane = tid & 31, wid = tid >> 5;
    int wm = (wid >> 2) * 64;
    int wn = (wid & 3) * 32;
    int g  = lane >> 2, tg = lane & 3;

    size_t by = (size_t)blockIdx.y * 128;
    size_t bx = (size_t)blockIdx.x * 128;

    int ar = tid >> 1, aj = tid & 1;
    int br = tid >> 3, bj = tid & 7;

    const float* Ab = A + (by + ar) * K;
    const float* Bb = B + bx;

    int mat = lane >> 3, rowin = lane & 7;
    unsigned a_off[4];
    #pragma unroll
    for (int mt = 0; mt < 4; mt++)
        a_off[mt] = (unsigned)(((wm + mt*16 + (mat & 1)*8 + rowin) * 36
                                + (mat >> 1) * 4) * 4);
    unsigned asb = smem_u32(Asf);

    float acc[4][4][4];
    #pragma unroll
    for (int i = 0; i < 4; i++)
        #pragma unroll
        for (int j = 0; j < 4; j++)
            #pragma unroll
            for (int f = 0; f < 4; f++) acc[i][j][f] = 0.f;

    auto load_stage = [&](int s, int k0) {
        unsigned ab = smem_u32(&Asf[s*GA_SZ + ar*36]);
        const float* asrc = Ab + k0;
        #pragma unroll
        for (int i = 0; i < 4; i++) {
            int c4 = aj + 2*i;
            cp16(ab + c4*16, asrc + c4*4);
        }
        unsigned bb = smem_u32(&Bsf[s*GB_SZ + br*136]);
        const float* bsrc = Bb + (size_t)(k0 + br) * N;
        #pragma unroll
        for (int i = 0; i < 4; i++) {
            int c4 = i*8 + bj;
            cp16(bb + c4*16, bsrc + c4*4);
        }
    };

    const int NIT = K >> 5;
    load_stage(0, 0);  CP_COMMIT();
    load_stage(1, 32); CP_COMMIT();

    #pragma unroll 1
    for (int it = 0; it < NIT; it++) {
        CP_WAIT1();
        __syncthreads();
        if (it + 2 < NIT) load_stage((it + 2) % 3, (it + 2) << 5);
        CP_COMMIT();

        unsigned abase = asb + (unsigned)((it % 3) * GA_SZ * 4);
        const unsigned* Bs = (const unsigned*)(Bsf + (it % 3) * GB_SZ);
        #pragma unroll
        for (int ks = 0; ks < 4; ks++) {
            int k8 = ks * 8;
            unsigned a[4][4], b[4][2];
            #pragma unroll
            for (int mt = 0; mt < 4; mt++)
                ldsm_x4(a[mt], abase + a_off[mt] + (unsigned)(k8 * 4));
            #pragma unroll
            for (int nt = 0; nt < 4; nt++) {
                int c = wn + nt * 8 + g;
                b[nt][0] = Bs[(k8+tg)*136 + c];
                b[nt][1] = Bs[(k8+tg+4)*136 + c];
            }
            #pragma unroll
            for (int mt = 0; mt < 4; mt++)
                #pragma unroll
                for (int nt = 0; nt < 4; nt++)
                    mma_tf32(acc[mt][nt], a[mt], b[nt]);
        }
    }

    #pragma unroll
    for (int mt = 0; mt < 4; mt++) {
        #pragma unroll
        for (int nt = 0; nt < 4; nt++) {
            size_t r = by + wm + mt * 16 + g;
            size_t c = bx + wn + nt * 8 + tg * 2;
            float v0 = acc[mt][nt][0], v1 = acc[mt][nt][1];
            float v2 = acc[mt][nt][2], v3 = acc[mt][nt][3];
            if (round_out) {
                v0 = f2tf_f(v0); v1 = f2tf_f(v1); v2 = f2tf_f(v2); v3 = f2tf_f(v3);
            }
            *(float2*)(C + r * N + c)       = make_float2(v0, v1);
            *(float2*)(C + (r + 8) * N + c) = make_float2(v2, v3);
        }
    }
}

// ---------------------------------------------------------------------------
// Fused attention PASS 1 ONLY: rowsums + ctx; exports inv to g_inv.
// cp.async pipelined, ldmatrix fragments (Ks/Es A-frags, Q B-frags).
// ---------------------------------------------------------------------------
#define KS_STRIDE 68
#define ES_STRIDE 132
#define QS_STRIDE 68
#define VS_STRIDE 72
#define OFF_ES 8704
#define OFF_Q0 25600
#define OFF_Q1 34304
#define OFF_V  43008
#define OFF_RP 52224
#define OFF_INV 52736
#define ATTN_SMEM ((OFF_INV + 128 + 64) * 4)   // 211,712 B

__global__ __launch_bounds__(256) void attn_fused(
    const float* __restrict__ res, float* __restrict__ ctx,
    float* __restrict__ inv_g)
{
    extern __shared__ unsigned sm[];
    unsigned* Ks = sm;
    unsigned* Es = sm + OFF_ES;
    unsigned* Qb0 = sm + OFF_Q0;
    unsigned* Qb1 = sm + OFF_Q1;
    unsigned* Vsu = sm + OFF_V;
    float* rp    = (float*)(sm + OFF_RP);
    float* inv_s = (float*)(sm + OFF_INV);

    int kb = (TT/128 - 1) - blockIdx.x;
    int bh = blockIdx.y;
    int b = bh / HH, h = bh % HH;
    int tid = threadIdx.x;
    int lane = tid & 31, wid = tid >> 5;
    int wm = (wid >> 2) * 64, wn = (wid & 3) * 32;
    int wm2 = (wid >> 1) * 32, wn2 = (wid & 1) * 32;
    int g = lane >> 2, tg = lane & 3;

    const float* Kg = res + (size_t)b * TT * TD3 + (size_t)h * HD;
    const float* Qg = res + (size_t)b * TT * TD3 + DD + (size_t)h * HD;
    const float* Vg = res + (size_t)b * TT * TD3 + 2 * DD + (size_t)h * HD;

    int qr = tid >> 1, qj = tid & 1;

    int mat = lane >> 3, rowin = lane & 7;
    int l16 = lane & 15;
    unsigned ks_off[4], es_off[2], q_off[4];
    #pragma unroll
    for (int mt = 0; mt < 4; mt++)
        ks_off[mt] = (unsigned)(((wm + mt*16 + (mat & 1)*8 + rowin) * KS_STRIDE
                                 + (mat >> 1) * 4) * 4);
    #pragma unroll
    for (int mt = 0; mt < 2; mt++)
        es_off[mt] = (unsigned)(((wm2 + mt*16 + (mat & 1)*8 + rowin) * ES_STRIDE
                                 + (mat >> 1) * 4) * 4);
    #pragma unroll
    for (int nt = 0; nt < 4; nt++)
        q_off[nt] = (unsigned)(((wn + nt*8 + (l16 & 7)) * QS_STRIDE
                                + (l16 >> 3) * 4) * 4);
    unsigned ksb = smem_u32(Ks);
    unsigned esb = smem_u32(Es);
    unsigned q0b = smem_u32(Qb0);
    unsigned q1b = smem_u32(Qb1);

    auto loadQ = [&](unsigned* buf, int qb) {
        unsigned base = smem_u32(&buf[qr * QS_STRIDE]);
        const float* src = Qg + (size_t)(qb * 128 + qr) * TD3;
        #pragma unroll
        for (int i = 0; i < 8; i++) {
            int c4 = qj + 2*i;
            cp16(base + c4*16, src + c4*4);
        }
    };
    auto loadV = [&](int qb) {
        unsigned base = smem_u32(&Vsu[qr * VS_STRIDE]);
        const float* src = Vg + (size_t)(qb * 128 + qr) * TD3;
        #pragma unroll
        for (int i = 0; i < 8; i++) {
            int c4 = qj + 2*i;
            cp16(base + c4*16, src + c4*4);
        }
    };

    // Stage K tile (already tf32 bits)
    {
        #pragma unroll
        for (int i = 0; i < 8; i++) {
            int ak = qj * 4 + i * 8;
            float4 v = *(const float4*)(Kg + (size_t)(kb * 128 + qr) * TD3 + ak);
            Ks[qr*KS_STRIDE + ak+0] = __float_as_uint(v.x);
            Ks[qr*KS_STRIDE + ak+1] = __float_as_uint(v.y);
            Ks[qr*KS_STRIDE + ak+2] = __float_as_uint(v.z);
            Ks[qr*KS_STRIDE + ak+3] = __float_as_uint(v.w);
        }
    }

    float rs0[4] = {0.f,0.f,0.f,0.f}, rs1[4] = {0.f,0.f,0.f,0.f};
    float acc2[2][4][4];
    #pragma unroll
    for (int i = 0; i < 2; i++)
        #pragma unroll
        for (int j = 0; j < 4; j++)
            #pragma unroll
            for (int f = 0; f < 4; f++) acc2[i][j][f] = 0.f;

    const float scale = 0.125f;

    loadQ(Qb0, 0); CP_COMMIT();
    #pragma unroll 1
    for (int qb = 0; qb <= kb; qb++) {
        unsigned qcb = (qb & 1) ? q1b : q0b;
        unsigned* Qnxt = (qb & 1) ? Qb0 : Qb1;
        loadV(qb); CP_COMMIT();
        CP_WAIT1();
        __syncthreads();

        float acc[4][4][4];
        #pragma unroll
        for (int i = 0; i < 4; i++)
            #pragma unroll
            for (int j = 0; j < 4; j++)
                #pragma unroll
                for (int f = 0; f < 4; f++) acc[i][j][f] = 0.f;

        #pragma unroll 4
        for (int ks = 0; ks < 8; ks++) {
            unsigned kbyte = (unsigned)(ks * 32);
            unsigned a[4][4], bf[4][2];
            #pragma unroll
            for (int mt = 0; mt < 4; mt++)
                ldsm_x4(a[mt], ksb + ks_off[mt] + kbyte);
            #pragma unroll
            for (int nt = 0; nt < 4; nt++)
                ldsm_x2(bf[nt], qcb + q_off[nt] + kbyte);
            #pragma unroll
            for (int mt = 0; mt < 4; mt++)
                #pragma unroll
                for (int nt = 0; nt < 4; nt++)
                    mma_tf32(acc[mt][nt], a[mt], bf[nt]);
        }

        if (qb < kb) loadQ(Qnxt, qb + 1);
        CP_COMMIT();

        bool diag = (qb == kb);
        #pragma unroll
        for (int mt = 0; mt < 4; mt++) {
            #pragma unroll
            for (int nt = 0; nt < 4; nt++) {
                int r = wm + mt * 16 + g;
                int c = wn + nt * 8 + tg * 2;
                int rg0 = kb * 128 + r, rg1 = rg0 + 8;
                int cg  = qb * 128 + c;
                float e0 = (diag && cg     > rg0) ? 0.f : __expf(acc[mt][nt][0] * scale);
                float e1 = (diag && cg + 1 > rg0) ? 0.f : __expf(acc[mt][nt][1] * scale);
                float e2 = (diag && cg     > rg1) ? 0.f : __expf(acc[mt][nt][2] * scale);
                float e3 = (diag && cg + 1 > rg1) ? 0.f : __expf(acc[mt][nt][3] * scale);
                rs0[mt] += e0 + e1;
                rs1[mt] += e2 + e3;
                *(uint2*)&Es[r*ES_STRIDE + c]     = make_uint2(f2tf(e0), f2tf(e1));
                *(uint2*)&Es[(r+8)*ES_STRIDE + c] = make_uint2(f2tf(e2), f2tf(e3));
            }
        }
        CP_WAIT1();
        __syncthreads();

        #pragma unroll 4
        for (int ks = 0; ks < 16; ks++) {
            int k8 = ks * 8;
            unsigned a[2][4], bf[4][2];
            #pragma unroll
            for (int mt = 0; mt < 2; mt++)
                ldsm_x4(a[mt], esb + es_off[mt] + (unsigned)(k8 * 4));
            #pragma unroll
            for (int nt = 0; nt < 4; nt++) {
                int c = wn2 + nt * 8 + g;
                bf[nt][0] = Vsu[(k8+tg)*VS_STRIDE + c];
                bf[nt][1] = Vsu[(k8+tg+4)*VS_STRIDE + c];
            }
            #pragma unroll
            for (int mt = 0; mt < 2; mt++)
                #pragma unroll
                for (int nt = 0; nt < 4; nt++)
                    mma_tf32(acc2[mt][nt], a[mt], bf[nt]);
        }
        __syncthreads();
    }

    // rowsum reduce -> inv (smem + export to global)
    #pragma unroll
    for (int mt = 0; mt < 4; mt++) {
        float s0 = rs0[mt], s1 = rs1[mt];
        s0 += __shfl_xor_sync(0xffffffffu, s0, 1);
        s0 += __shfl_xor_sync(0xffffffffu, s0, 2);
        s1 += __shfl_xor_sync(0xffffffffu, s1, 1);
        s1 += __shfl_xor_sync(0xffffffffu, s1, 2);
        if (tg == 0) {
            rp[(wm + mt*16 + g)*4 + (wid & 3)]     = s0;
            rp[(wm + mt*16 + g + 8)*4 + (wid & 3)] = s1;
        }
    }
    __syncthreads();
    if (tid < 128) {
        float iv = 1.f / (rp[tid*4] + rp[tid*4+1] + rp[tid*4+2] + rp[tid*4+3]);
        inv_s[tid] = iv;
        inv_g[(size_t)bh * TT + kb * 128 + tid] = iv;
    }
    __syncthreads();

    // scale ctx, write tf32-rounded (consumed by tensor out-GEMM)
    {
        float* Cg = ctx + (size_t)b * TT * DD + (size_t)h * HD;
        #pragma unroll
        for (int mt = 0; mt < 2; mt++) {
            int r2 = wm2 + mt * 16 + g;
            float il = inv_s[r2], ih = inv_s[r2 + 8];
            #pragma unroll
            for (int nt = 0; nt < 4; nt++) {
                size_t rA = (size_t)kb * 128 + r2;
                int c = wn2 + nt * 8 + tg * 2;
                *(float2*)(Cg + rA * DD + c) =
                    make_float2(f2tf_f(acc2[mt][nt][0] * il), f2tf_f(acc2[mt][nt][1] * il));
                *(float2*)(Cg + (rA + 8) * DD + c) =
                    make_float2(f2tf_f(acc2[mt][nt][2] * ih), f2tf_f(acc2[mt][nt][3] * ih));
            }
        }
    }
}

// ---------------------------------------------------------------------------
// attn_write: one 128x128 tile per CTA. Zero tiles early-exit; compute tiles
// recompute scores (res L2-resident), apply exp*inv, write attn once.
// Bit-identical mma order to pass 1. 2 CTAs/SM.
// ---------------------------------------------------------------------------
#define AW_QS 8704
#define AW_SMEM (2 * 8704 * 4)   // 69,632 B

__global__ __launch_bounds__(256, 2) void attn_write(
    const float* __restrict__ res, const float* __restrict__ inv_g,
    float* __restrict__ attn)
{
    extern __shared__ unsigned sm2[];
    unsigned* Ks = sm2;
    unsigned* Qs = sm2 + AW_QS;

    int qb = blockIdx.x, kb = blockIdx.y, bh = blockIdx.z;
    int b = bh / HH, h = bh % HH;
    int tid = threadIdx.x;
    float* out = attn + ((size_t)bh * TT + (size_t)kb * 128) * TT + (size_t)qb * 128;

    if (qb > kb) {   // fully masked -> zeros
        float4 z = make_float4(0.f, 0.f, 0.f, 0.f);
        #pragma unroll
        for (int i = tid; i < 128 * 32; i += 256)
            *(float4*)(out + (size_t)(i >> 5) * TT + (i & 31) * 4) = z;
        return;
    }

    int lane = tid & 31, wid = tid >> 5;
    int wm = (wid >> 2) * 64, wn = (wid & 3) * 32;
    int g = lane >> 2, tg = lane & 3;

    const float* Kg = res + (size_t)b * TT * TD3 + (size_t)h * HD;
    const float* Qg = res + (size_t)b * TT * TD3 + DD + (size_t)h * HD;

    int qr = tid >> 1, qj = tid & 1;
    {
        unsigned kb_s = smem_u32(&Ks[qr * KS_STRIDE]);
        unsigned qb_s = smem_u32(&Qs[qr * QS_STRIDE]);
        const float* ksrc = Kg + (size_t)(kb * 128 + qr) * TD3;
        const float* qsrc = Qg + (size_t)(qb * 128 + qr) * TD3;
        #pragma unroll
        for (int i = 0; i < 8; i++) {
            int c4 = qj + 2*i;
            cp16(kb_s + c4*16, ksrc + c4*4);
            cp16(qb_s + c4*16, qsrc + c4*4);
        }
    }
    CP_COMMIT();

    int mat = lane >> 3, rowin = lane & 7;
    int l16 = lane & 15;
    unsigned ks_off[4], q_off[4];
    #pragma unroll
    for (int mt = 0; mt < 4; mt++)
        ks_off[mt] = (unsigned)(((wm + mt*16 + (mat & 1)*8 + rowin) * KS_STRIDE
                                 + (mat >> 1) * 4) * 4);
    #pragma unroll
    for (int nt = 0; nt < 4; nt++)
        q_off[nt] = (unsigned)(((wn + nt*8 + (l16 & 7)) * QS_STRIDE
                                + (l16 >> 3) * 4) * 4);
    unsigned ksb = smem_u32(Ks);
    unsigned qsb = smem_u32(Qs);

    float iv0[4], iv1[4];
    #pragma unroll
    for (int mt = 0; mt < 4; mt++) {
        iv0[mt] = inv_g[(size_t)bh * TT + kb * 128 + wm + mt*16 + g];
        iv1[mt] = inv_g[(size_t)bh * TT + kb * 128 + wm + mt*16 + g + 8];
    }

    CP_WAIT0();
    __syncthreads();

    float acc[4][4][4];
    #pragma unroll
    for (int i = 0; i < 4; i++)
        #pragma unroll
        for (int j = 0; j < 4; j++)
            #pragma unroll
            for (int f = 0; f < 4; f++) acc[i][j][f] = 0.f;

    #pragma unroll 4
    for (int ks = 0; ks < 8; ks++) {
        unsigned kbyte = (unsigned)(ks * 32);
        unsigned a[4][4], bf[4][2];
        #pragma unroll
        for (int mt = 0; mt < 4; mt++)
            ldsm_x4(a[mt], ksb + ks_off[mt] + kbyte);
        #pragma unroll
        for (int nt = 0; nt < 4; nt++)
            ldsm_x2(bf[nt], qsb + q_off[nt] + kbyte);
        #pragma unroll
        for (int mt = 0; mt < 4; mt++)
            #pragma unroll
            for (int nt = 0; nt < 4; nt++)
                mma_tf32(acc[mt][nt], a[mt], bf[nt]);
    }

    const float scale = 0.125f;
    bool diag = (qb == kb);
    #pragma unroll
    for (int mt = 0; mt < 4; mt++) {
        #pragma unroll
        for (int nt = 0; nt < 4; nt++) {
            int r = wm + mt * 16 + g;
            int c = wn + nt * 8 + tg * 2;
            int rg0 = kb * 128 + r, rg1 = rg0 + 8;
            int cg  = qb * 128 + c;
            float e0 = (diag && cg     > rg0) ? 0.f : __expf(acc[mt][nt][0]*scale) * iv0[mt];
            float e1 = (diag && cg + 1 > rg0) ? 0.f : __expf(acc[mt][nt][1]*scale) * iv0[mt];
            float e2 = (diag && cg     > rg1) ? 0.f : __expf(acc[mt][nt][2]*scale) * iv1[mt];
            float e3 = (diag && cg + 1 > rg1) ? 0.f : __expf(acc[mt][nt][3]*scale) * iv1[mt];
            *(float2*)(out + (size_t)r * TT + c)       = make_float2(e0, e1);
            *(float2*)(out + (size_t)(r + 8) * TT + c) = make_float2(e2, e3);
        }
    }
}

// ---------------------------------------------------------------------------
extern "C" void kernel_launch(void* const* d_in, const int* in_sizes, int n_in,
                              void* d_out, int out_size)
{
    const float* X     = (const float*)d_in[0];
    const float* W_KQV = (const float*)d_in[1];
    const float* W_out = (const float*)d_in[2];

    const size_t OUT_E  = (size_t)BB * TT * DD;
    const size_t ATTN_E = (size_t)BB * HH * TT * TT;

    float* res_p;  cudaGetSymbolAddress((void**)&res_p,  g_res);
    float* ctx_p;  cudaGetSymbolAddress((void**)&ctx_p,  g_ctx);
    float* attn_s; cudaGetSymbolAddress((void**)&attn_s, g_attn);
    float* xr_p;   cudaGetSymbolAddress((void**)&xr_p,   g_Xr);
    float* wrk_p;  cudaGetSymbolAddress((void**)&wrk_p,  g_WrKQV);
    float* wro_p;  cudaGetSymbolAddress((void**)&wro_p,  g_WrOut);
    float* inv_p;  cudaGetSymbolAddress((void**)&inv_p,  g_inv);

    float* out_p = nullptr;
    float* attn_p;
    size_t osz = (size_t)out_size;
    if (osz >= OUT_E + ATTN_E) {
        out_p  = (float*)d_out;
        attn_p = (float*)d_out + OUT_E;
    } else if (osz == ATTN_E) {
        attn_p = (float*)d_out;
    } else {
        out_p  = (float*)d_out;
        attn_p = attn_s;
    }

    cudaFuncSetAttribute(gemm_tf32_nn,
                         cudaFuncAttributeMaxDynamicSharedMemorySize, GEMM_SMEM);
    cudaFuncSetAttribute(attn_fused,
                         cudaFuncAttributeMaxDynamicSharedMemorySize, ATTN_SMEM);
    cudaFuncSetAttribute(attn_write,
                         cudaFuncAttributeMaxDynamicSharedMemorySize, AW_SMEM);

    // 0) prep: tf32-round X and weights once (W_KQV/W_out already [K,N])
    round_copy<<<512, 256>>>(X,     xr_p,  (BB*TT*DD) / 4);
    round_copy<<<512, 256>>>(W_KQV, wrk_p, (DD*TD3) / 4);
    round_copy<<<256, 256>>>(W_out, wro_p, (DD*DD) / 4);

    // 1) QKV projection (writes res tf32-rounded)
    {
        dim3 grid(TD3 / 128, (BB * TT) / 128);
        gemm_tf32_nn<<<grid, 256, GEMM_SMEM>>>(xr_p, wrk_p, res_p, BB * TT, TD3, DD, 1);
    }
    // 2) pass 1: ctx (tf32-rounded) + inv export
    {
        dim3 grid(TT / 128, BB * HH);
        attn_fused<<<grid, 256, ATTN_SMEM>>>(res_p, ctx_p, inv_p);
    }
    // 3) write normalized attn (one tile per CTA, high occupancy)
    {
        dim3 grid(TT / 128, TT / 128, BB * HH);
        attn_write<<<grid, 256, AW_SMEM>>>(res_p, inv_p, attn_p);
    }
    // 4) out = ctx @ W_out (full fp32 output)
    if (out_p) {
        dim3 grid(DD / 128, (BB * TT) / 128);
        gemm_tf32_nn<<<grid, 256, GEMM_SMEM>>>(ctx_p, wro_p, out_p, BB * TT, DD, DD, 0);
    }
}

// round 15
// speedup vs baseline: 1.6786x; 1.5848x over previous
#include <cuda_runtime.h>
#include <cuda_fp16.h>
#include <cstddef>

#define BB 2
#define TT 2048
#define DD 1024
#define HH 16
#define HD 64
#define TD3 (3*DD)

// Scratch (device globals: allowed; cudaMalloc is not)
__device__ __half g_Xh[(size_t)BB*TT*DD];         // X fp16
__device__ __half g_WhKQV[(size_t)TD3*DD];        // W_KQV^T [3D][D] fp16
__device__ __half g_WhOut[(size_t)DD*DD];         // W_out^T [D][D] fp16
__device__ __half g_resh[(size_t)BB*TT*TD3];      // QKV projection fp16
__device__ __half g_ctxh[(size_t)BB*TT*DD];       // context fp16
__device__ float  g_inv[(size_t)BB*HH*TT];        // per-row 1/softmax-sum
__device__ float  g_attn[(size_t)BB*HH*TT*TT];    // attn fallback

// ---------------------------------------------------------------------------
// helpers
// ---------------------------------------------------------------------------
__device__ __forceinline__ void mma_f16(float* c, const unsigned* a, const unsigned* b) {
    asm volatile("mma.sync.aligned.m16n8k16.row.col.f32.f16.f16.f32 "
        "{%0,%1,%2,%3}, {%4,%5,%6,%7}, {%8,%9}, {%0,%1,%2,%3};"
        : "+f"(c[0]), "+f"(c[1]), "+f"(c[2]), "+f"(c[3])
        : "r"(a[0]), "r"(a[1]), "r"(a[2]), "r"(a[3]), "r"(b[0]), "r"(b[1]));
}
__device__ __forceinline__ unsigned smem_u32(const void* p) {
    return (unsigned)__cvta_generic_to_shared(p);
}
__device__ __forceinline__ void cp16(unsigned dst, const void* src) {
    asm volatile("cp.async.cg.shared.global [%0], [%1], 16;" :: "r"(dst), "l"(src));
}
#define CP_COMMIT() asm volatile("cp.async.commit_group;" ::: "memory")
#define CP_WAIT1()  asm volatile("cp.async.wait_group 1;" ::: "memory")
#define CP_WAIT0()  asm volatile("cp.async.wait_group 0;" ::: "memory")

__device__ __forceinline__ void ldsm_x4(unsigned* r, unsigned addr) {
    asm volatile("ldmatrix.sync.aligned.m8n8.x4.shared.b16 {%0,%1,%2,%3}, [%4];"
        : "=r"(r[0]), "=r"(r[1]), "=r"(r[2]), "=r"(r[3]) : "r"(addr));
}
__device__ __forceinline__ void ldsm_x4t(unsigned* r, unsigned addr) {
    asm volatile("ldmatrix.sync.aligned.m8n8.x4.trans.shared.b16 {%0,%1,%2,%3}, [%4];"
        : "=r"(r[0]), "=r"(r[1]), "=r"(r[2]), "=r"(r[3]) : "r"(addr));
}

// ---------------------------------------------------------------------------
// prep kernels
// ---------------------------------------------------------------------------
__global__ __launch_bounds__(256) void to_half(
    const float* __restrict__ in, __half* __restrict__ out, int n4)
{
    int i = blockIdx.x * 256 + threadIdx.x;
    int stride = gridDim.x * 256;
    for (; i < n4; i += stride) {
        float4 v = *(const float4*)(in + (size_t)i * 4);
        __half2 h0 = __floats2half2_rn(v.x, v.y);
        __half2 h1 = __floats2half2_rn(v.z, v.w);
        ((__half2*)out)[(size_t)i * 2]     = h0;
        ((__half2*)out)[(size_t)i * 2 + 1] = h1;
    }
}

// in[R][C] float -> out[C][R] fp16
__global__ __launch_bounds__(256) void transpose_half(
    const float* __restrict__ in, __half* __restrict__ out, int R, int C)
{
    __shared__ float t[32][33];
    int bx = blockIdx.x * 32;   // C
    int by = blockIdx.y * 32;   // R
    int tx = threadIdx.x & 31, ty = threadIdx.x >> 5;
    #pragma unroll
    for (int i = 0; i < 4; i++)
        t[ty + i*8][tx] = in[(size_t)(by + ty + i*8) * C + bx + tx];
    __syncthreads();
    #pragma unroll
    for (int i = 0; i < 4; i++)
        out[(size_t)(bx + ty + i*8) * R + by + tx] = __float2half_rn(t[tx][ty + i*8]);
}

// ---------------------------------------------------------------------------
// NT fp16 GEMM: C[M,N] = A[M,K] @ Bt[N,K]^T, fp16 operands, fp32 accum.
// block 128x128, k-chunk 64, 3-stage cp.async, all fragments via ldmatrix.
// ---------------------------------------------------------------------------
#define GH_STRIDE 72
#define GH_SZ (128*GH_STRIDE)                 // halfs per stage per matrix
#define GEMM_SMEM (3*2*GH_SZ*2)               // 110,592 B

__global__ __launch_bounds__(256, 2) void gemm_f16_nt(
    const __half* __restrict__ A, const __half* __restrict__ Bt,
    void* __restrict__ Cv, int M, int N, int K, int out_half)
{
    extern __shared__ __half gsh[];
    __half* As = gsh;                // [3][128][72]
    __half* Bs = gsh + 3*GH_SZ;      // [3][128][72]

    int tid = threadIdx.x;
    int lane = tid & 31, wid = tid >> 5;
    int wm = (wid >> 2) * 64;
    int wn = (wid & 3) * 32;
    int g  = lane >> 2, tg = lane & 3;

    size_t by = (size_t)blockIdx.y * 128;
    size_t bx = (size_t)blockIdx.x * 128;

    int r = tid >> 1, j = tid & 1;
    const __half* Ab = A  + (by + r) * K;
    const __half* Bb = Bt + (bx + r) * K;

    int mat = lane >> 3, rowin = lane & 7;
    unsigned a_off[4], b_off[2];
    #pragma unroll
    for (int mt = 0; mt < 4; mt++)
        a_off[mt] = (unsigned)(((wm + mt*16 + (mat & 1)*8 + rowin) * GH_STRIDE
                                + (mat >> 1) * 8) * 2);
    #pragma unroll
    for (int ntp = 0; ntp < 2; ntp++)
        b_off[ntp] = (unsigned)(((wn + ntp*16 + (mat >> 1)*8 + rowin) * GH_STRIDE
                                 + (mat & 1) * 8) * 2);
    unsigned asb = smem_u32(As);
    unsigned bsb = smem_u32(Bs);

    float acc[4][4][4];
    #pragma unroll
    for (int i = 0; i < 4; i++)
        #pragma unroll
        for (int jj = 0; jj < 4; jj++)
            #pragma unroll
            for (int f = 0; f < 4; f++) acc[i][jj][f] = 0.f;

    auto load_stage = [&](int s, int k0) {
        unsigned ad = smem_u32(&As[s*GH_SZ + r*GH_STRIDE]);
        unsigned bd = smem_u32(&Bs[s*GH_SZ + r*GH_STRIDE]);
        const __half* asrc = Ab + k0;
        const __half* bsrc = Bb + k0;
        #pragma unroll
        for (int i = 0; i < 4; i++) {
            int c4 = j * 4 + i;
            cp16(ad + c4*16, asrc + c4*8);
            cp16(bd + c4*16, bsrc + c4*8);
        }
    };

    const int NIT = K >> 6;
    load_stage(0, 0);  CP_COMMIT();
    load_stage(1, 64); CP_COMMIT();

    #pragma unroll 1
    for (int it = 0; it < NIT; it++) {
        CP_WAIT1();
        __syncthreads();
        if (it + 2 < NIT) load_stage((it + 2) % 3, (it + 2) << 6);
        CP_COMMIT();

        unsigned abase = asb + (unsigned)((it % 3) * GH_SZ * 2);
        unsigned bbase = bsb + (unsigned)((it % 3) * GH_SZ * 2);
        #pragma unroll
        for (int ks = 0; ks < 4; ks++) {
            unsigned kb2 = (unsigned)(ks * 32);
            unsigned a[4][4], bq[2][4];
            #pragma unroll
            for (int mt = 0; mt < 4; mt++)
                ldsm_x4(a[mt], abase + a_off[mt] + kb2);
            #pragma unroll
            for (int ntp = 0; ntp < 2; ntp++)
                ldsm_x4(bq[ntp], bbase + b_off[ntp] + kb2);
            #pragma unroll
            for (int mt = 0; mt < 4; mt++)
                #pragma unroll
                for (int nt = 0; nt < 4; nt++)
                    mma_f16(acc[mt][nt], a[mt], &bq[nt >> 1][(nt & 1) * 2]);
        }
    }

    #pragma unroll
    for (int mt = 0; mt < 4; mt++) {
        #pragma unroll
        for (int nt = 0; nt < 4; nt++) {
            size_t rr = by + wm + mt * 16 + g;
            size_t cc = bx + wn + nt * 8 + tg * 2;
            if (out_half) {
                __half* C = (__half*)Cv;
                *(__half2*)(C + rr * N + cc) =
                    __floats2half2_rn(acc[mt][nt][0], acc[mt][nt][1]);
                *(__half2*)(C + (rr + 8) * N + cc) =
                    __floats2half2_rn(acc[mt][nt][2], acc[mt][nt][3]);
            } else {
                float* C = (float*)Cv;
                *(float2*)(C + rr * N + cc)       = make_float2(acc[mt][nt][0], acc[mt][nt][1]);
                *(float2*)(C + (rr + 8) * N + cc) = make_float2(acc[mt][nt][2], acc[mt][nt][3]);
            }
        }
    }
}

// ---------------------------------------------------------------------------
// attn_fused (pass 1): scores mma -> exp -> Es -> ctx mma; rowsums -> inv.
// All fp16 operands; exp in fp32. Exports inv; writes ctx fp16.
// ---------------------------------------------------------------------------
#define TS 72                       // K/Q/V tile stride (halfs)
#define ES_STRIDE 136
#define H_KS 0
#define H_ES 9216
#define H_Q0 26624
#define H_Q1 35840
#define H_V  45056
#define H_END 54272                 // halfs
#define B_RP (H_END*2)              // bytes: rp floats
#define B_INV (B_RP + 2048)
#define ATTN_SMEM (B_INV + 512 + 64)

__global__ __launch_bounds__(256) void attn_fused(
    const __half* __restrict__ res, __half* __restrict__ ctx,
    float* __restrict__ inv_g)
{
    extern __shared__ __half ash[];
    __half* Ks  = ash + H_KS;
    __half* Es  = ash + H_ES;
    __half* Qb0 = ash + H_Q0;
    __half* Qb1 = ash + H_Q1;
    __half* Vs  = ash + H_V;
    float* rp    = (float*)((char*)ash + B_RP);
    float* inv_s = (float*)((char*)ash + B_INV);

    int kb = (TT/128 - 1) - blockIdx.x;
    int bh = blockIdx.y;
    int b = bh / HH, h = bh % HH;
    int tid = threadIdx.x;
    int lane = tid & 31, wid = tid >> 5;
    int wm = (wid >> 2) * 64, wn = (wid & 3) * 32;
    int wm2 = (wid >> 1) * 32, wn2 = (wid & 1) * 32;
    int g = lane >> 2, tg = lane & 3;

    const __half* Kg = res + (size_t)b * TT * TD3 + (size_t)h * HD;
    const __half* Qg = res + (size_t)b * TT * TD3 + DD + (size_t)h * HD;
    const __half* Vg = res + (size_t)b * TT * TD3 + 2 * DD + (size_t)h * HD;

    int qr = tid >> 1, qj = tid & 1;

    int mat = lane >> 3, rowin = lane & 7;
    unsigned ks_off[4], es_off[2], q_off[2], v_off[2];
    #pragma unroll
    for (int mt = 0; mt < 4; mt++)
        ks_off[mt] = (unsigned)(((wm + mt*16 + (mat & 1)*8 + rowin) * TS
                                 + (mat >> 1) * 8) * 2);
    #pragma unroll
    for (int mt = 0; mt < 2; mt++)
        es_off[mt] = (unsigned)(((wm2 + mt*16 + (mat & 1)*8 + rowin) * ES_STRIDE
                                 + (mat >> 1) * 8) * 2);
    #pragma unroll
    for (int ntp = 0; ntp < 2; ntp++) {
        q_off[ntp] = (unsigned)(((wn + ntp*16 + (mat >> 1)*8 + rowin) * TS
                                 + (mat & 1) * 8) * 2);
        v_off[ntp] = (unsigned)((((mat & 1)*8 + rowin) * TS
                                 + wn2 + ntp*16 + (mat >> 1)*8) * 2);
    }
    unsigned ksb = smem_u32(Ks);
    unsigned esb = smem_u32(Es);
    unsigned q0b = smem_u32(Qb0);
    unsigned q1b = smem_u32(Qb1);
    unsigned vsb = smem_u32(Vs);

    auto loadK = [&]() {
        unsigned base = smem_u32(&Ks[qr * TS]);
        const __half* src = Kg + (size_t)(kb * 128 + qr) * TD3;
        #pragma unroll
        for (int i = 0; i < 4; i++) {
            int c4 = qj * 4 + i;
            cp16(base + c4*16, src + c4*8);
        }
    };
    auto loadQ = [&](__half* buf, int qb) {
        unsigned base = smem_u32(&buf[qr * TS]);
        const __half* src = Qg + (size_t)(qb * 128 + qr) * TD3;
        #pragma unroll
        for (int i = 0; i < 4; i++) {
            int c4 = qj * 4 + i;
            cp16(base + c4*16, src + c4*8);
        }
    };
    auto loadV = [&](int qb) {
        unsigned base = smem_u32(&Vs[qr * TS]);
        const __half* src = Vg + (size_t)(qb * 128 + qr) * TD3;
        #pragma unroll
        for (int i = 0; i < 4; i++) {
            int c4 = qj * 4 + i;
            cp16(base + c4*16, src + c4*8);
        }
    };

    float rs0[4] = {0.f,0.f,0.f,0.f}, rs1[4] = {0.f,0.f,0.f,0.f};
    float acc2[2][4][4];
    #pragma unroll
    for (int i = 0; i < 2; i++)
        #pragma unroll
        for (int jj = 0; jj < 4; jj++)
            #pragma unroll
            for (int f = 0; f < 4; f++) acc2[i][jj][f] = 0.f;

    const float scale = 0.125f;

    loadK(); loadQ(Qb0, 0); CP_COMMIT();
    #pragma unroll 1
    for (int qb = 0; qb <= kb; qb++) {
        unsigned qcb = (qb & 1) ? q1b : q0b;
        __half* Qnxt = (qb & 1) ? Qb0 : Qb1;
        loadV(qb); CP_COMMIT();
        CP_WAIT1();
        __syncthreads();

        float acc[4][4][4];
        #pragma unroll
        for (int i = 0; i < 4; i++)
            #pragma unroll
            for (int jj = 0; jj < 4; jj++)
                #pragma unroll
                for (int f = 0; f < 4; f++) acc[i][jj][f] = 0.f;

        #pragma unroll
        for (int ks = 0; ks < 4; ks++) {
            unsigned kb2 = (unsigned)(ks * 32);
            unsigned a[4][4], bq[2][4];
            #pragma unroll
            for (int mt = 0; mt < 4; mt++)
                ldsm_x4(a[mt], ksb + ks_off[mt] + kb2);
            #pragma unroll
            for (int ntp = 0; ntp < 2; ntp++)
                ldsm_x4(bq[ntp], qcb + q_off[ntp] + kb2);
            #pragma unroll
            for (int mt = 0; mt < 4; mt++)
                #pragma unroll
                for (int nt = 0; nt < 4; nt++)
                    mma_f16(acc[mt][nt], a[mt], &bq[nt >> 1][(nt & 1) * 2]);
        }

        if (qb < kb) loadQ(Qnxt, qb + 1);
        CP_COMMIT();

        bool diag = (qb == kb);
        #pragma unroll
        for (int mt = 0; mt < 4; mt++) {
            #pragma unroll
            for (int nt = 0; nt < 4; nt++) {
                int r = wm + mt * 16 + g;
                int c = wn + nt * 8 + tg * 2;
                int rg0 = kb * 128 + r, rg1 = rg0 + 8;
                int cg  = qb * 128 + c;
                float e0 = (diag && cg     > rg0) ? 0.f : __expf(acc[mt][nt][0] * scale);
                float e1 = (diag && cg + 1 > rg0) ? 0.f : __expf(acc[mt][nt][1] * scale);
                float e2 = (diag && cg     > rg1) ? 0.f : __expf(acc[mt][nt][2] * scale);
                float e3 = (diag && cg + 1 > rg1) ? 0.f : __expf(acc[mt][nt][3] * scale);
                rs0[mt] += e0 + e1;
                rs1[mt] += e2 + e3;
                *(__half2*)&Es[r*ES_STRIDE + c]     = __floats2half2_rn(e0, e1);
                *(__half2*)&Es[(r+8)*ES_STRIDE + c] = __floats2half2_rn(e2, e3);
            }
        }
        CP_WAIT1();
        __syncthreads();

        // ctx mma: acc2 += Es[128 x 128] @ V[128 x 64]
        #pragma unroll
        for (int ks = 0; ks < 8; ks++) {
            unsigned a2[2][4], bv[2][4];
            #pragma unroll
            for (int mt = 0; mt < 2; mt++)
                ldsm_x4(a2[mt], esb + es_off[mt] + (unsigned)(ks * 32));
            #pragma unroll
            for (int ntp = 0; ntp < 2; ntp++)
                ldsm_x4t(bv[ntp], vsb + v_off[ntp] + (unsigned)(ks * 16 * TS * 2));
            #pragma unroll
            for (int mt = 0; mt < 2; mt++)
                #pragma unroll
                for (int nt = 0; nt < 4; nt++)
                    mma_f16(acc2[mt][nt], a2[mt], &bv[nt >> 1][(nt & 1) * 2]);
        }
        __syncthreads();
    }

    // rowsum reduce -> inv (smem + export)
    #pragma unroll
    for (int mt = 0; mt < 4; mt++) {
        float s0 = rs0[mt], s1 = rs1[mt];
        s0 += __shfl_xor_sync(0xffffffffu, s0, 1);
        s0 += __shfl_xor_sync(0xffffffffu, s0, 2);
        s1 += __shfl_xor_sync(0xffffffffu, s1, 1);
        s1 += __shfl_xor_sync(0xffffffffu, s1, 2);
        if (tg == 0) {
            rp[(wm + mt*16 + g)*4 + (wid & 3)]     = s0;
            rp[(wm + mt*16 + g + 8)*4 + (wid & 3)] = s1;
        }
    }
    __syncthreads();
    if (tid < 128) {
        float iv = 1.f / (rp[tid*4] + rp[tid*4+1] + rp[tid*4+2] + rp[tid*4+3]);
        inv_s[tid] = iv;
        inv_g[(size_t)bh * TT + kb * 128 + tid] = iv;
    }
    __syncthreads();

    // scale ctx, write fp16 (consumed by out-GEMM)
    {
        __half* Cg = ctx + (size_t)b * TT * DD + (size_t)h * HD;
        #pragma unroll
        for (int mt = 0; mt < 2; mt++) {
            int r2 = wm2 + mt * 16 + g;
            float il = inv_s[r2], ih = inv_s[r2 + 8];
            #pragma unroll
            for (int nt = 0; nt < 4; nt++) {
                size_t rA = (size_t)kb * 128 + r2;
                int c = wn2 + nt * 8 + tg * 2;
                *(__half2*)(Cg + rA * DD + c) =
                    __floats2half2_rn(acc2[mt][nt][0] * il, acc2[mt][nt][1] * il);
                *(__half2*)(Cg + (rA + 8) * DD + c) =
                    __floats2half2_rn(acc2[mt][nt][2] * ih, acc2[mt][nt][3] * ih);
            }
        }
    }
}

// ---------------------------------------------------------------------------
// attn_write: one 128x128 tile per CTA, fp16 score recompute (bit-identical
// to pass 1), exp*inv, single attn write. Zero tiles early-exit.
// ---------------------------------------------------------------------------
#define AW_SMEM (2 * 9216 * 2)   // 36,864 B

__global__ __launch_bounds__(256, 2) void attn_write(
    const __half* __restrict__ res, const float* __restrict__ inv_g,
    float* __restrict__ attn)
{
    extern __shared__ __half ash2[];
    __half* Ks = ash2;
    __half* Qs = ash2 + 9216;

    int qb = blockIdx.x, kb = blockIdx.y, bh = blockIdx.z;
    int b = bh / HH, h = bh % HH;
    int tid = threadIdx.x;
    float* out = attn + ((size_t)bh * TT + (size_t)kb * 128) * TT + (size_t)qb * 128;

    if (qb > kb) {   // fully masked -> zeros
        float4 z = make_float4(0.f, 0.f, 0.f, 0.f);
        #pragma unroll
        for (int i = tid; i < 128 * 32; i += 256)
            *(float4*)(out + (size_t)(i >> 5) * TT + (i & 31) * 4) = z;
        return;
    }

    int lane = tid & 31, wid = tid >> 5;
    int wm = (wid >> 2) * 64, wn = (wid & 3) * 32;
    int g = lane >> 2, tg = lane & 3;

    const __half* Kg = res + (size_t)b * TT * TD3 + (size_t)h * HD;
    const __half* Qg = res + (size_t)b * TT * TD3 + DD + (size_t)h * HD;

    int qr = tid >> 1, qj = tid & 1;
    {
        unsigned kd = smem_u32(&Ks[qr * TS]);
        unsigned qd = smem_u32(&Qs[qr * TS]);
        const __half* ksrc = Kg + (size_t)(kb * 128 + qr) * TD3;
        const __half* qsrc = Qg + (size_t)(qb * 128 + qr) * TD3;
        #pragma unroll
        for (int i = 0; i < 4; i++) {
            int c4 = qj * 4 + i;
            cp16(kd + c4*16, ksrc + c4*8);
            cp16(qd + c4*16, qsrc + c4*8);
        }
    }
    CP_COMMIT();

    int mat = lane >> 3, rowin = lane & 7;
    unsigned ks_off[4], q_off[2];
    #pragma unroll
    for (int mt = 0; mt < 4; mt++)
        ks_off[mt] = (unsigned)(((wm + mt*16 + (mat & 1)*8 + rowin) * TS
                                 + (mat >> 1) * 8) * 2);
    #pragma unroll
    for (int ntp = 0; ntp < 2; ntp++)
        q_off[ntp] = (unsigned)(((wn + ntp*16 + (mat >> 1)*8 + rowin) * TS
                                 + (mat & 1) * 8) * 2);
    unsigned ksb = smem_u32(Ks);
    unsigned qsb = smem_u32(Qs);

    float iv0[4], iv1[4];
    #pragma unroll
    for (int mt = 0; mt < 4; mt++) {
        iv0[mt] = inv_g[(size_t)bh * TT + kb * 128 + wm + mt*16 + g];
        iv1[mt] = inv_g[(size_t)bh * TT + kb * 128 + wm + mt*16 + g + 8];
    }

    CP_WAIT0();
    __syncthreads();

    float acc[4][4][4];
    #pragma unroll
    for (int i = 0; i < 4; i++)
        #pragma unroll
        for (int jj = 0; jj < 4; jj++)
            #pragma unroll
            for (int f = 0; f < 4; f++) acc[i][jj][f] = 0.f;

    #pragma unroll
    for (int ks = 0; ks < 4; ks++) {
        unsigned kb2 = (unsigned)(ks * 32);
        unsigned a[4][4], bq[2][4];
        #pragma unroll
        for (int mt = 0; mt < 4; mt++)
            ldsm_x4(a[mt], ksb + ks_off[mt] + kb2);
        #pragma unroll
        for (int ntp = 0; ntp < 2; ntp++)
            ldsm_x4(bq[ntp], qsb + q_off[ntp] + kb2);
        #pragma unroll
        for (int mt = 0; mt < 4; mt++)
            #pragma unroll
            for (int nt = 0; nt < 4; nt++)
                mma_f16(acc[mt][nt], a[mt], &bq[nt >> 1][(nt & 1) * 2]);
    }

    const float scale = 0.125f;
    bool diag = (qb == kb);
    #pragma unroll
    for (int mt = 0; mt < 4; mt++) {
        #pragma unroll
        for (int nt = 0; nt < 4; nt++) {
            int r = wm + mt * 16 + g;
            int c = wn + nt * 8 + tg * 2;
            int rg0 = kb * 128 + r, rg1 = rg0 + 8;
            int cg  = qb * 128 + c;
            float e0 = (diag && cg     > rg0) ? 0.f : __expf(acc[mt][nt][0]*scale) * iv0[mt];
            float e1 = (diag && cg + 1 > rg0) ? 0.f : __expf(acc[mt][nt][1]*scale) * iv0[mt];
            float e2 = (diag && cg     > rg1) ? 0.f : __expf(acc[mt][nt][2]*scale) * iv1[mt];
            float e3 = (diag && cg + 1 > rg1) ? 0.f : __expf(acc[mt][nt][3]*scale) * iv1[mt];
            *(float2*)(out + (size_t)r * TT + c)       = make_float2(e0, e1);
            *(float2*)(out + (size_t)(r + 8) * TT + c) = make_float2(e2, e3);
        }
    }
}

// ---------------------------------------------------------------------------
extern "C" void kernel_launch(void* const* d_in, const int* in_sizes, int n_in,
                              void* d_out, int out_size)
{
    const float* X     = (const float*)d_in[0];
    const float* W_KQV = (const float*)d_in[1];
    const float* W_out = (const float*)d_in[2];

    const size_t OUT_E  = (size_t)BB * TT * DD;
    const size_t ATTN_E = (size_t)BB * HH * TT * TT;

    __half* xh_p;  cudaGetSymbolAddress((void**)&xh_p,  g_Xh);
    __half* whk_p; cudaGetSymbolAddress((void**)&whk_p, g_WhKQV);
    __half* who_p; cudaGetSymbolAddress((void**)&who_p, g_WhOut);
    __half* resh_p; cudaGetSymbolAddress((void**)&resh_p, g_resh);
    __half* ctxh_p; cudaGetSymbolAddress((void**)&ctxh_p, g_ctxh);
    float* inv_p;  cudaGetSymbolAddress((void**)&inv_p,  g_inv);
    float* attn_s; cudaGetSymbolAddress((void**)&attn_s, g_attn);

    float* out_p = nullptr;
    float* attn_p;
    size_t osz = (size_t)out_size;
    if (osz >= OUT_E + ATTN_E) {
        out_p  = (float*)d_out;
        attn_p = (float*)d_out + OUT_E;
    } else if (osz == ATTN_E) {
        attn_p = (float*)d_out;
    } else {
        out_p  = (float*)d_out;
        attn_p = attn_s;
    }

    cudaFuncSetAttribute(gemm_f16_nt,
                         cudaFuncAttributeMaxDynamicSharedMemorySize, GEMM_SMEM);
    cudaFuncSetAttribute(attn_fused,
                         cudaFuncAttributeMaxDynamicSharedMemorySize, ATTN_SMEM);
    cudaFuncSetAttribute(attn_write,
                         cudaFuncAttributeMaxDynamicSharedMemorySize, AW_SMEM);

    // 0) prep: fp16-round X; transpose+round weights to [N][K] fp16
    to_half<<<512, 256>>>(X, xh_p, (BB*TT*DD) / 4);
    {
        dim3 grid(TD3 / 32, DD / 32);
        transpose_half<<<grid, 256>>>(W_KQV, whk_p, DD, TD3);
    }
    {
        dim3 grid(DD / 32, DD / 32);
        transpose_half<<<grid, 256>>>(W_out, who_p, DD, DD);
    }

    // 1) QKV projection (fp16 out)
    {
        dim3 grid(TD3 / 128, (BB * TT) / 128);
        gemm_f16_nt<<<grid, 256, GEMM_SMEM>>>(xh_p, whk_p, resh_p, BB * TT, TD3, DD, 1);
    }
    // 2) pass 1: ctx (fp16) + inv export
    {
        dim3 grid(TT / 128, BB * HH);
        attn_fused<<<grid, 256, ATTN_SMEM>>>(resh_p, ctxh_p, inv_p);
    }
    // 3) write normalized attn (one tile per CTA, high occupancy)
    {
        dim3 grid(TT / 128, TT / 128, BB * HH);
        attn_write<<<grid, 256, AW_SMEM>>>(resh_p, inv_p, attn_p);
    }
    // 4) out = ctx @ W_out (fp32 output)
    if (out_p) {
        dim3 grid(DD / 128, (BB * TT) / 128);
        gemm_f16_nt<<<grid, 256, GEMM_SMEM>>>(ctxh_p, who_p, out_p, BB * TT, DD, DD, 0);
    }
}